// round 11
// baseline (speedup 1.0000x reference)
#include <cuda_runtime.h>
#include <cuda_bf16.h>
#include <cstdint>
#include <math.h>

// Problem dims (fixed)
#define BB 4
#define SS 4096
#define DD 1024

// ---------------------------------------------------------------------------
// Helpers
// ---------------------------------------------------------------------------
__device__ __forceinline__ uint32_t smem_u32(const void* p) {
    uint32_t a;
    asm("{ .reg .u64 t; cvta.to.shared.u64 t, %1; cvt.u32.u64 %0, t; }" : "=r"(a) : "l"(p));
    return a;
}

#define CP_ASYNC16(saddr, gptr) \
    asm volatile("cp.async.cg.shared.global [%0], [%1], 16;" :: "r"(saddr), "l"(gptr))
#define CP_COMMIT() asm volatile("cp.async.commit_group;")

__device__ __forceinline__ void ldsm4(uint32_t (&r)[4], uint32_t addr) {
    asm volatile("ldmatrix.sync.aligned.m8n8.x4.shared.b16 {%0,%1,%2,%3}, [%4];"
                 : "=r"(r[0]), "=r"(r[1]), "=r"(r[2]), "=r"(r[3]) : "r"(addr));
}

__device__ __forceinline__ void mma16816(float (&d)[4], const uint32_t (&a)[4],
                                         uint32_t b0, uint32_t b1) {
    asm volatile("mma.sync.aligned.m16n8k16.row.col.f32.bf16.bf16.f32 "
                 "{%0,%1,%2,%3}, {%4,%5,%6,%7}, {%8,%9}, {%0,%1,%2,%3};"
                 : "+f"(d[0]), "+f"(d[1]), "+f"(d[2]), "+f"(d[3])
                 : "r"(a[0]), "r"(a[1]), "r"(a[2]), "r"(a[3]), "r"(b0), "r"(b1));
}

// Fast exp on the FMA pipe (no MUFU)
__device__ __forceinline__ float fast_exp(float x) {
    float y = x * 1.4426950408889634f;
    y = fmaxf(y, -120.0f);
    float n = rintf(y);
    float f = y - n;
    float p =              1.3333642e-3f;
    p = fmaf(p, f, 9.6181291e-3f);
    p = fmaf(p, f, 5.5504109e-2f);
    p = fmaf(p, f, 2.4022651e-1f);
    p = fmaf(p, f, 6.9314718e-1f);
    p = fmaf(p, f, 1.0f);
    float s = __int_as_float(((int)n + 127) << 23);
    return p * s;
}

// ---------------------------------------------------------------------------
// Scratch
// ---------------------------------------------------------------------------
#define NSD ((size_t)BB * SS * DD)
#define NSS ((size_t)BB * SS * SS)
#define NW  ((size_t)DD * DD)

__device__ __align__(16) __nv_bfloat16 g_iq_h[NSD], g_iq_l[NSD];
__device__ __align__(16) __nv_bfloat16 g_ik_h[NSD], g_ik_l[NSD];
__device__ __align__(16) __nv_bfloat16 g_iv_h[NSD], g_iv_l[NSD];
__device__ __align__(16) __nv_bfloat16 g_w1_h[NW], g_w1_l[NW];     // WhT
__device__ __align__(16) __nv_bfloat16 g_w2_h[NW], g_w2_l[NW];     // WkT
__device__ __align__(16) __nv_bfloat16 g_w3_h[NW], g_w3_l[NW];     // WvT
__device__ __align__(16) __nv_bfloat16 g_w4_h[NW], g_w4_l[NW];     // WoT
__device__ __align__(16) __nv_bfloat16 g_whp_h[NW], g_whp_l[NW];   // Wh (plain)
__device__ __align__(16) __nv_bfloat16 g_wck_h[NW], g_wck_l[NW];   // (Wh·Wk)^T
__device__ __align__(16) __nv_bfloat16 g_wcv_h[NW], g_wcv_l[NW];   // (Wh·Wv)^T
__device__ __align__(16) float g_bck[DD];
__device__ __align__(16) float g_bcv[DD];
__device__ __align__(16) __nv_bfloat16 g_q_h[NSD],  g_q_l[NSD];
__device__ __align__(16) __nv_bfloat16 g_k_h[NSD],  g_k_l[NSD];
__device__ __align__(16) __nv_bfloat16 g_vt_h[NSD], g_vt_l[NSD];
__device__ __align__(16) __nv_bfloat16 g_o_h[NSD],  g_o_l[NSD];
__device__ __align__(16) __nv_bfloat16 g_p_h[NSS],  g_p_l[NSS];
__device__ __align__(16) float g_v[NSD];
__device__ __align__(16) float g_P[NSS];

// ---------------------------------------------------------------------------
// bf16x3 HMMA GEMM: C = scale*(A @ B^T) (+ bias)
//   A: hi/lo bf16 [M,K]; B: hi/lo bf16 [N,K]; both K-major.
//   CTA tile 128(M) x 256(N), BK=16, 6-stage cp.async (5 chunks in flight),
//   512 threads = 16 warps (4m x 4n), warp tile 32x64.
//   48B smem rows: 8 rows mod 128B hit banks {0,48,96,16,64,112,32,80}
//   -> conflict-free ldmatrix.
// ---------------------------------------------------------------------------
#define ROWB 48
#define AMATB (128 * ROWB)              // 6144 B
#define BMATB (256 * ROWB)              // 12288 B
#define STAGEB (2 * AMATB + 2 * BMATB)  // 36864 B
#define NSTAGE 6
#define GEMM_SMEM (NSTAGE * STAGEB)     // 221184 B
#define GTHREADS 512

template<bool HAS_BIAS, bool OUT_F32, bool OUT_HL>
__global__ __launch_bounds__(GTHREADS, 1)
void gemm_bf16x3(const __nv_bfloat16* __restrict__ Ah, const __nv_bfloat16* __restrict__ Al,
                 const __nv_bfloat16* __restrict__ Bh, const __nv_bfloat16* __restrict__ Bl,
                 const float* __restrict__ bias,
                 float* __restrict__ Cf,
                 __nv_bfloat16* __restrict__ Ch, __nv_bfloat16* __restrict__ Cl,
                 int M, int N, int K, float scale,
                 size_t sA, size_t sB, size_t sC)
{
    extern __shared__ char smem[];
    const uint32_t sbase = smem_u32(smem);
    const int tid  = threadIdx.x;
    const int lane = tid & 31;
    const int wid  = tid >> 5;
    const int wm   = wid & 3;      // 0..3 -> m (x32)
    const int wn   = wid >> 2;     // 0..3 -> n (x64)
    const size_t z = blockIdx.z;
    Ah += z * sA;  Al += z * sA;
    Bh += z * sB;  Bl += z * sB;
    if (OUT_F32) Cf += z * sC;
    if (OUT_HL)  { Ch += z * sC; Cl += z * sC; }
    const int m0 = blockIdx.y * 128;
    const int n0 = blockIdx.x * 256;
    const int NC = K >> 4;          // K/16 chunks

    // --- stage loader: 3 x 16B cp.async per thread ---
    auto load_stage = [&](int c, int s) {
        const uint32_t st = sbase + s * STAGEB;
        const int k0 = c * 16;
        {   // A: 512 chunks (128 rows x 2 kc x 2 mats)
            int row = tid >> 2;
            int sub = tid & 3;
            int mat = sub >> 1, kc = sub & 1;
            uint32_t so = st + mat * AMATB + row * ROWB + kc * 16;
            size_t go = (size_t)(m0 + row) * K + k0 + kc * 8;
            CP_ASYNC16(so, (mat ? Al : Ah) + go);
        }
        #pragma unroll
        for (int i = 0; i < 2; i++) {  // B: 1024 chunks (256 rows x 2 kc x 2 mats)
            int cid = tid + i * GTHREADS;
            int row = cid >> 2;
            int sub = cid & 3;
            int mat = sub >> 1, kc = sub & 1;
            uint32_t so = st + 2 * AMATB + mat * BMATB + row * ROWB + kc * 16;
            size_t go = (size_t)(n0 + row) * K + k0 + kc * 8;
            CP_ASYNC16(so, (mat ? Bl : Bh) + go);
        }
        CP_COMMIT();
    };

    float acc[2][8][4];
    #pragma unroll
    for (int mi = 0; mi < 2; mi++)
        #pragma unroll
        for (int ni = 0; ni < 8; ni++)
            #pragma unroll
            for (int r = 0; r < 4; r++) acc[mi][ni][r] = 0.f;

    #pragma unroll
    for (int s = 0; s < 5; s++) load_stage(s, s);

    const int a_row = lane & 15;
    const int a_k8  = lane >> 4;
    const int b_row = (lane & 7) + ((lane >> 4) << 3);
    const int b_k8  = (lane >> 3) & 1;

    int stage = 0;
    for (int c = 0; c < NC; c++) {
        const int rem = NC - 1 - c;   // groups that will still complete after c
        if      (rem >= 4) asm volatile("cp.async.wait_group 4;");
        else if (rem == 3) asm volatile("cp.async.wait_group 3;");
        else if (rem == 2) asm volatile("cp.async.wait_group 2;");
        else if (rem == 1) asm volatile("cp.async.wait_group 1;");
        else               asm volatile("cp.async.wait_group 0;");
        __syncthreads();

        if (c + 5 < NC) {
            int ns = stage + 5; if (ns >= NSTAGE) ns -= NSTAGE;
            load_stage(c + 5, ns);
        }

        const uint32_t stg = sbase + stage * STAGEB;
        uint32_t ah[2][4], al[2][4];
        #pragma unroll
        for (int mi = 0; mi < 2; mi++) {
            uint32_t ra = stg + (wm * 32 + mi * 16 + a_row) * ROWB + a_k8 * 16;
            ldsm4(ah[mi], ra);
            ldsm4(al[mi], ra + AMATB);
        }
        #pragma unroll
        for (int ng = 0; ng < 4; ng++) {
            uint32_t rb = stg + 2 * AMATB
                        + (wn * 64 + ng * 16 + b_row) * ROWB + b_k8 * 16;
            uint32_t bh4[4], bl4[4];
            ldsm4(bh4, rb);
            ldsm4(bl4, rb + BMATB);
            #pragma unroll
            for (int half = 0; half < 2; half++) {
                const int ni = ng * 2 + half;
                #pragma unroll
                for (int mi = 0; mi < 2; mi++) {
                    mma16816(acc[mi][ni], ah[mi], bh4[half * 2], bh4[half * 2 + 1]);
                    mma16816(acc[mi][ni], ah[mi], bl4[half * 2], bl4[half * 2 + 1]);
                    mma16816(acc[mi][ni], al[mi], bh4[half * 2], bh4[half * 2 + 1]);
                }
            }
        }
        if (++stage == NSTAGE) stage = 0;
    }

    // --- epilogue: direct global stores ---
    #pragma unroll
    for (int mi = 0; mi < 2; mi++) {
        const int r0 = m0 + wm * 32 + mi * 16 + (lane >> 2);
        #pragma unroll
        for (int ni = 0; ni < 8; ni++) {
            const int col = n0 + wn * 64 + ni * 8 + (lane & 3) * 2;
            float c0 = acc[mi][ni][0] * scale;
            float c1 = acc[mi][ni][1] * scale;
            float c2 = acc[mi][ni][2] * scale;
            float c3 = acc[mi][ni][3] * scale;
            if (HAS_BIAS) {
                float bx = __ldg(bias + col), by = __ldg(bias + col + 1);
                c0 += bx; c1 += by; c2 += bx; c3 += by;
            }
            if (OUT_F32) {
                *(float2*)(Cf + (size_t)r0 * N + col)       = make_float2(c0, c1);
                *(float2*)(Cf + (size_t)(r0 + 8) * N + col) = make_float2(c2, c3);
            }
            if (OUT_HL) {
                __nv_bfloat16 h0 = __float2bfloat16_rn(c0);
                __nv_bfloat16 h1 = __float2bfloat16_rn(c1);
                __nv_bfloat16 h2 = __float2bfloat16_rn(c2);
                __nv_bfloat16 h3 = __float2bfloat16_rn(c3);
                *(__nv_bfloat162*)(Ch + (size_t)r0 * N + col)       = __nv_bfloat162(h0, h1);
                *(__nv_bfloat162*)(Ch + (size_t)(r0 + 8) * N + col) = __nv_bfloat162(h2, h3);
                *(__nv_bfloat162*)(Cl + (size_t)r0 * N + col) = __nv_bfloat162(
                    __float2bfloat16_rn(c0 - __bfloat162float(h0)),
                    __float2bfloat16_rn(c1 - __bfloat162float(h1)));
                *(__nv_bfloat162*)(Cl + (size_t)(r0 + 8) * N + col) = __nv_bfloat162(
                    __float2bfloat16_rn(c2 - __bfloat162float(h2)),
                    __float2bfloat16_rn(c3 - __bfloat162float(h3)));
            }
        }
    }
}

// ---------------------------------------------------------------------------
// fp32 -> bf16 hi/lo elementwise split
// ---------------------------------------------------------------------------
__global__ __launch_bounds__(256)
void split_kernel(const float4* __restrict__ src,
                  __nv_bfloat162* __restrict__ dh, __nv_bfloat162* __restrict__ dl, int n4)
{
    int i = blockIdx.x * blockDim.x + threadIdx.x;
    if (i >= n4) return;
    float4 v = src[i];
    __nv_bfloat16 hx = __float2bfloat16_rn(v.x), hy = __float2bfloat16_rn(v.y);
    __nv_bfloat16 hz = __float2bfloat16_rn(v.z), hw = __float2bfloat16_rn(v.w);
    dh[i * 2 + 0] = __nv_bfloat162(hx, hy);
    dh[i * 2 + 1] = __nv_bfloat162(hz, hw);
    dl[i * 2 + 0] = __nv_bfloat162(__float2bfloat16_rn(v.x - __bfloat162float(hx)),
                                   __float2bfloat16_rn(v.y - __bfloat162float(hy)));
    dl[i * 2 + 1] = __nv_bfloat162(__float2bfloat16_rn(v.z - __bfloat162float(hz)),
                                   __float2bfloat16_rn(v.w - __bfloat162float(hw)));
}

// ---------------------------------------------------------------------------
// fp32 [R,C] -> transposed bf16 hi/lo [C,R]  (batched via z)
// ---------------------------------------------------------------------------
__global__ __launch_bounds__(256)
void transpose_split_kernel(const float* __restrict__ src,
                            __nv_bfloat16* __restrict__ dh, __nv_bfloat16* __restrict__ dl,
                            int R, int C)
{
    __shared__ float tile[32][33];
    size_t z = blockIdx.z;
    size_t nb = (size_t)R * C;
    src += z * nb; dh += z * nb; dl += z * nb;
    int c0 = blockIdx.x * 32, r0 = blockIdx.y * 32;
    int tx = threadIdx.x & 31, ty = threadIdx.x >> 5;
    for (int i = ty; i < 32; i += 8)
        tile[i][tx] = src[(size_t)(r0 + i) * C + c0 + tx];
    __syncthreads();
    for (int i = ty; i < 32; i += 8) {
        float v = tile[tx][i];
        __nv_bfloat16 hi = __float2bfloat16_rn(v);
        size_t off = (size_t)(c0 + i) * R + r0 + tx;
        dh[off] = hi;
        dl[off] = __float2bfloat16_rn(v - __bfloat162float(hi));
    }
}

// ---------------------------------------------------------------------------
// Combined bias: bc[i] = b2[i] + sum_l bh[l] * W[l*DD + i]
// ---------------------------------------------------------------------------
__global__ __launch_bounds__(256)
void bias_combine_kernel(const float* __restrict__ bh, const float* __restrict__ W,
                         const float* __restrict__ b2, float* __restrict__ bc)
{
    int i = blockIdx.x * 256 + threadIdx.x;
    float s = b2[i];
    for (int l = 0; l < DD; l++) s += bh[l] * W[(size_t)l * DD + i];
    bc[i] = s;
}

// ---------------------------------------------------------------------------
// Row softmax: fp32 scores -> bf16 hi/lo attention weights (FMA-pipe exp)
// ---------------------------------------------------------------------------
__global__ __launch_bounds__(256)
void softmax_kernel(const float* __restrict__ P,
                    __nv_bfloat16* __restrict__ Ph, __nv_bfloat16* __restrict__ Pl)
{
    const size_t roff = (size_t)blockIdx.x * SS;
    const float* row = P + roff;
    const int tid = threadIdx.x;

    float4 v[4];
    #pragma unroll
    for (int i = 0; i < 4; i++)
        v[i] = *(const float4*)(row + (size_t)(tid + i * 256) * 4);

    float m = -INFINITY;
    #pragma unroll
    for (int i = 0; i < 4; i++)
        m = fmaxf(m, fmaxf(fmaxf(v[i].x, v[i].y), fmaxf(v[i].z, v[i].w)));
    #pragma unroll
    for (int off = 16; off > 0; off >>= 1)
        m = fmaxf(m, __shfl_xor_sync(0xFFFFFFFFu, m, off));

    __shared__ float smax[8], ssum[8];
    const int warp = tid >> 5, lane = tid & 31;
    if (lane == 0) smax[warp] = m;
    __syncthreads();
    if (warp == 0) {
        float t = (lane < 8) ? smax[lane] : -INFINITY;
        #pragma unroll
        for (int off = 4; off > 0; off >>= 1)
            t = fmaxf(t, __shfl_xor_sync(0xFFFFFFFFu, t, off));
        if (lane == 0) smax[0] = t;
    }
    __syncthreads();
    m = smax[0];

    float s = 0.f;
    #pragma unroll
    for (int i = 0; i < 4; i++) {
        v[i].x = fast_exp(v[i].x - m); v[i].y = fast_exp(v[i].y - m);
        v[i].z = fast_exp(v[i].z - m); v[i].w = fast_exp(v[i].w - m);
        s += v[i].x + v[i].y + v[i].z + v[i].w;
    }
    #pragma unroll
    for (int off = 16; off > 0; off >>= 1)
        s += __shfl_xor_sync(0xFFFFFFFFu, s, off);
    if (lane == 0) ssum[warp] = s;
    __syncthreads();
    if (warp == 0) {
        float t = (lane < 8) ? ssum[lane] : 0.f;
        #pragma unroll
        for (int off = 4; off > 0; off >>= 1)
            t += __shfl_xor_sync(0xFFFFFFFFu, t, off);
        if (lane == 0) ssum[0] = t;
    }
    __syncthreads();
    const float inv = 1.0f / ssum[0];

    #pragma unroll
    for (int i = 0; i < 4; i++) {
        size_t base = roff + (size_t)(tid + i * 256) * 4;
        float a = v[i].x * inv, b = v[i].y * inv, c = v[i].z * inv, d = v[i].w * inv;
        __nv_bfloat16 ha = __float2bfloat16_rn(a), hb = __float2bfloat16_rn(b);
        __nv_bfloat16 hc = __float2bfloat16_rn(c), hd = __float2bfloat16_rn(d);
        *(__nv_bfloat162*)(Ph + base)     = __nv_bfloat162(ha, hb);
        *(__nv_bfloat162*)(Ph + base + 2) = __nv_bfloat162(hc, hd);
        *(__nv_bfloat162*)(Pl + base) = __nv_bfloat162(
            __float2bfloat16_rn(a - __bfloat162float(ha)),
            __float2bfloat16_rn(b - __bfloat162float(hb)));
        *(__nv_bfloat162*)(Pl + base + 2) = __nv_bfloat162(
            __float2bfloat16_rn(c - __bfloat162float(hc)),
            __float2bfloat16_rn(d - __bfloat162float(hd)));
    }
}

// ---------------------------------------------------------------------------
// Launch
// ---------------------------------------------------------------------------
extern "C" void kernel_launch(void* const* d_in, const int* in_sizes, int n_in,
                              void* d_out, int out_size)
{
    const float* query = (const float*)d_in[0];
    const float* key_  = (const float*)d_in[1];
    const float* value = (const float*)d_in[2];
    const float* Wh    = (const float*)d_in[3];
    const float* bh    = (const float*)d_in[4];
    const float* Wk    = (const float*)d_in[5];
    const float* bk    = (const float*)d_in[6];
    const float* Wv    = (const float*)d_in[7];
    const float* bv    = (const float*)d_in[8];
    const float* Wo    = (const float*)d_in[9];
    const float* bo    = (const float*)d_in[10];
    float* out = (float*)d_out;

    struct Ptrs {
        __nv_bfloat16 *iq_h, *iq_l, *ik_h, *ik_l, *iv_h, *iv_l;
        __nv_bfloat16 *w1_h, *w1_l, *w2_h, *w2_l, *w3_h, *w3_l, *w4_h, *w4_l;
        __nv_bfloat16 *whp_h, *whp_l, *wck_h, *wck_l, *wcv_h, *wcv_l;
        __nv_bfloat16 *q_h, *q_l, *k_h, *k_l, *vt_h, *vt_l, *o_h, *o_l;
        __nv_bfloat16 *p_h, *p_l;
        float *bck, *bcv, *v, *P;
    };
    static Ptrs p = {};
    static bool inited = false;
    if (!inited) {
        inited = true;
        cudaGetSymbolAddress((void**)&p.iq_h, g_iq_h); cudaGetSymbolAddress((void**)&p.iq_l, g_iq_l);
        cudaGetSymbolAddress((void**)&p.ik_h, g_ik_h); cudaGetSymbolAddress((void**)&p.ik_l, g_ik_l);
        cudaGetSymbolAddress((void**)&p.iv_h, g_iv_h); cudaGetSymbolAddress((void**)&p.iv_l, g_iv_l);
        cudaGetSymbolAddress((void**)&p.w1_h, g_w1_h); cudaGetSymbolAddress((void**)&p.w1_l, g_w1_l);
        cudaGetSymbolAddress((void**)&p.w2_h, g_w2_h); cudaGetSymbolAddress((void**)&p.w2_l, g_w2_l);
        cudaGetSymbolAddress((void**)&p.w3_h, g_w3_h); cudaGetSymbolAddress((void**)&p.w3_l, g_w3_l);
        cudaGetSymbolAddress((void**)&p.w4_h, g_w4_h); cudaGetSymbolAddress((void**)&p.w4_l, g_w4_l);
        cudaGetSymbolAddress((void**)&p.whp_h, g_whp_h); cudaGetSymbolAddress((void**)&p.whp_l, g_whp_l);
        cudaGetSymbolAddress((void**)&p.wck_h, g_wck_h); cudaGetSymbolAddress((void**)&p.wck_l, g_wck_l);
        cudaGetSymbolAddress((void**)&p.wcv_h, g_wcv_h); cudaGetSymbolAddress((void**)&p.wcv_l, g_wcv_l);
        cudaGetSymbolAddress((void**)&p.q_h,  g_q_h);  cudaGetSymbolAddress((void**)&p.q_l,  g_q_l);
        cudaGetSymbolAddress((void**)&p.k_h,  g_k_h);  cudaGetSymbolAddress((void**)&p.k_l,  g_k_l);
        cudaGetSymbolAddress((void**)&p.vt_h, g_vt_h); cudaGetSymbolAddress((void**)&p.vt_l, g_vt_l);
        cudaGetSymbolAddress((void**)&p.o_h,  g_o_h);  cudaGetSymbolAddress((void**)&p.o_l,  g_o_l);
        cudaGetSymbolAddress((void**)&p.p_h,  g_p_h);  cudaGetSymbolAddress((void**)&p.p_l,  g_p_l);
        cudaGetSymbolAddress((void**)&p.bck,  g_bck);  cudaGetSymbolAddress((void**)&p.bcv,  g_bcv);
        cudaGetSymbolAddress((void**)&p.v,    g_v);    cudaGetSymbolAddress((void**)&p.P,    g_P);
        cudaFuncSetAttribute(gemm_bf16x3<true,  false, true >, cudaFuncAttributeMaxDynamicSharedMemorySize, GEMM_SMEM);
        cudaFuncSetAttribute(gemm_bf16x3<true,  true,  false>, cudaFuncAttributeMaxDynamicSharedMemorySize, GEMM_SMEM);
        cudaFuncSetAttribute(gemm_bf16x3<false, true,  false>, cudaFuncAttributeMaxDynamicSharedMemorySize, GEMM_SMEM);
        cudaFuncSetAttribute(gemm_bf16x3<false, false, true >, cudaFuncAttributeMaxDynamicSharedMemorySize, GEMM_SMEM);
    }

    const int M = BB * SS;                  // 16384
    const size_t sd = (size_t)SS * DD;
    const size_t ss = (size_t)SS * SS;
    dim3 blk(GTHREADS);

    // --- prep: split inputs / weights, fold chained projections ---
    {
        int n4 = (int)(NSD / 4);
        int grid = (n4 + 255) / 256;
        split_kernel<<<grid, 256>>>((const float4*)query, (__nv_bfloat162*)p.iq_h, (__nv_bfloat162*)p.iq_l, n4);
        split_kernel<<<grid, 256>>>((const float4*)key_,  (__nv_bfloat162*)p.ik_h, (__nv_bfloat162*)p.ik_l, n4);
        split_kernel<<<grid, 256>>>((const float4*)value, (__nv_bfloat162*)p.iv_h, (__nv_bfloat162*)p.iv_l, n4);
        int w4 = (int)(NW / 4);
        split_kernel<<<(w4 + 255) / 256, 256>>>((const float4*)Wh, (__nv_bfloat162*)p.whp_h, (__nv_bfloat162*)p.whp_l, w4);
        dim3 gw(DD / 32, DD / 32, 1);
        transpose_split_kernel<<<gw, 256>>>(Wh, p.w1_h, p.w1_l, DD, DD);
        transpose_split_kernel<<<gw, 256>>>(Wk, p.w2_h, p.w2_l, DD, DD);
        transpose_split_kernel<<<gw, 256>>>(Wv, p.w3_h, p.w3_l, DD, DD);
        transpose_split_kernel<<<gw, 256>>>(Wo, p.w4_h, p.w4_l, DD, DD);

        // combined weights: (Wh·Wk)^T = WkT @ Wh(plain)^T-form, (Wh·Wv)^T likewise
        dim3 gc(DD / 256, DD / 128, 1);
        gemm_bf16x3<false, false, true><<<gc, blk, GEMM_SMEM>>>(
            p.w2_h, p.w2_l, p.whp_h, p.whp_l, nullptr, nullptr, p.wck_h, p.wck_l,
            DD, DD, DD, 1.f, 0, 0, 0);
        gemm_bf16x3<false, false, true><<<gc, blk, GEMM_SMEM>>>(
            p.w3_h, p.w3_l, p.whp_h, p.whp_l, nullptr, nullptr, p.wcv_h, p.wcv_l,
            DD, DD, DD, 1.f, 0, 0, 0);
        bias_combine_kernel<<<DD / 256, 256>>>(bh, Wk, bk, p.bck);
        bias_combine_kernel<<<DD / 256, 256>>>(bh, Wv, bv, p.bcv);
    }

    dim3 gproj(DD / 256, M / 128, 1);       // (4, 128)

    // 1) q = query @ Wh + bh
    gemm_bf16x3<true, false, true><<<gproj, blk, GEMM_SMEM>>>(
        p.iq_h, p.iq_l, p.w1_h, p.w1_l, bh, nullptr, p.q_h, p.q_l,
        M, DD, DD, 1.f, 0, 0, 0);
    // 2) k = key @ (Wh Wk) + (bh Wk + bk)
    gemm_bf16x3<true, false, true><<<gproj, blk, GEMM_SMEM>>>(
        p.ik_h, p.ik_l, p.wck_h, p.wck_l, p.bck, nullptr, p.k_h, p.k_l,
        M, DD, DD, 1.f, 0, 0, 0);
    // 3) v = value @ (Wh Wv) + (bh Wv + bv)  -> fp32, then transpose+split
    gemm_bf16x3<true, true, false><<<gproj, blk, GEMM_SMEM>>>(
        p.iv_h, p.iv_l, p.wcv_h, p.wcv_l, p.bcv, p.v, nullptr, nullptr,
        M, DD, DD, 1.f, 0, 0, 0);
    {
        dim3 gv(DD / 32, SS / 32, BB);
        transpose_split_kernel<<<gv, 256>>>(p.v, p.vt_h, p.vt_l, SS, DD);
    }

    // 4) P = (q @ k^T) / 1024   (batched)
    dim3 gqk(SS / 256, SS / 128, BB);       // (16, 32, 4)
    gemm_bf16x3<false, true, false><<<gqk, blk, GEMM_SMEM>>>(
        p.q_h, p.q_l, p.k_h, p.k_l, nullptr, p.P, nullptr, nullptr,
        SS, SS, DD, 1.0f / (float)DD, sd, sd, ss);

    // 5) softmax -> bf16 hi/lo attn (FMA-pipe exp)
    softmax_kernel<<<BB * SS, 256>>>(p.P, p.p_h, p.p_l);

    // 6) o = attn @ v  == attn @ (vT)^T  (batched)
    dim3 gpv(DD / 256, SS / 128, BB);       // (4, 32, 4)
    gemm_bf16x3<false, false, true><<<gpv, blk, GEMM_SMEM>>>(
        p.p_h, p.p_l, p.vt_h, p.vt_l, nullptr, nullptr, p.o_h, p.o_l,
        SS, DD, SS, 1.f, ss, sd, sd);

    // 7) out = o @ Wo + bo  -> fp32
    gemm_bf16x3<true, true, false><<<gproj, blk, GEMM_SMEM>>>(
        p.o_h, p.o_l, p.w4_h, p.w4_l, bo, out, nullptr, nullptr,
        M, DD, DD, 1.f, 0, 0, 0);
}

// round 16
// speedup vs baseline: 1.2692x; 1.2692x over previous
#include <cuda_runtime.h>
#include <cuda_bf16.h>
#include <cstdint>
#include <math.h>

// Problem dims (fixed)
#define BB 4
#define SS 4096
#define DD 1024

// ---------------------------------------------------------------------------
// Helpers
// ---------------------------------------------------------------------------
__device__ __forceinline__ uint32_t smem_u32(const void* p) {
    uint32_t a;
    asm("{ .reg .u64 t; cvta.to.shared.u64 t, %1; cvt.u32.u64 %0, t; }" : "=r"(a) : "l"(p));
    return a;
}

#define CP_ASYNC16(saddr, gptr) \
    asm volatile("cp.async.cg.shared.global [%0], [%1], 16;" :: "r"(saddr), "l"(gptr))
#define CP_COMMIT() asm volatile("cp.async.commit_group;")

__device__ __forceinline__ void ldsm4(uint32_t (&r)[4], uint32_t addr) {
    asm volatile("ldmatrix.sync.aligned.m8n8.x4.shared.b16 {%0,%1,%2,%3}, [%4];"
                 : "=r"(r[0]), "=r"(r[1]), "=r"(r[2]), "=r"(r[3]) : "r"(addr));
}

__device__ __forceinline__ void mma16816(float (&d)[4], const uint32_t (&a)[4],
                                         uint32_t b0, uint32_t b1) {
    asm volatile("mma.sync.aligned.m16n8k16.row.col.f32.bf16.bf16.f32 "
                 "{%0,%1,%2,%3}, {%4,%5,%6,%7}, {%8,%9}, {%0,%1,%2,%3};"
                 : "+f"(d[0]), "+f"(d[1]), "+f"(d[2]), "+f"(d[3])
                 : "r"(a[0]), "r"(a[1]), "r"(a[2]), "r"(a[3]), "r"(b0), "r"(b1));
}

// Fast exp on the FMA pipe (no MUFU)
__device__ __forceinline__ float fast_exp(float x) {
    float y = x * 1.4426950408889634f;
    y = fmaxf(y, -120.0f);
    float n = rintf(y);
    float f = y - n;
    float p =              1.3333642e-3f;
    p = fmaf(p, f, 9.6181291e-3f);
    p = fmaf(p, f, 5.5504109e-2f);
    p = fmaf(p, f, 2.4022651e-1f);
    p = fmaf(p, f, 6.9314718e-1f);
    p = fmaf(p, f, 1.0f);
    float s = __int_as_float(((int)n + 127) << 23);
    return p * s;
}

// ---------------------------------------------------------------------------
// Scratch
// ---------------------------------------------------------------------------
#define NSD ((size_t)BB * SS * DD)
#define NSS ((size_t)BB * SS * SS)
#define NW  ((size_t)DD * DD)

__device__ __align__(16) __nv_bfloat16 g_iq_h[NSD], g_iq_l[NSD];
__device__ __align__(16) __nv_bfloat16 g_ik_h[NSD], g_ik_l[NSD];
__device__ __align__(16) __nv_bfloat16 g_iv_h[NSD], g_iv_l[NSD];
__device__ __align__(16) __nv_bfloat16 g_w1_h[NW], g_w1_l[NW];       // WhT
__device__ __align__(16) __nv_bfloat16 g_w2_h[NW], g_w2_l[NW];       // WkT
__device__ __align__(16) __nv_bfloat16 g_w3_h[NW], g_w3_l[NW];       // WvT
__device__ __align__(16) __nv_bfloat16 g_w4_h[NW], g_w4_l[NW];       // WoT
__device__ __align__(16) __nv_bfloat16 g_whp_h[NW], g_whp_l[NW];     // Wh (plain)
__device__ __align__(16) __nv_bfloat16 g_wck_h[NW],  g_wck_l[NW];    // (Wh·Wk)^T
__device__ __align__(16) __nv_bfloat16 g_whwv_h[NW], g_whwv_l[NW];   // (Wh·Wv) plain
__device__ __align__(16) __nv_bfloat16 g_wcvo_h[NW], g_wcvo_l[NW];   // (Wh·Wv·Wo)^T
__device__ __align__(16) float g_bck[DD];
__device__ __align__(16) float g_bcv[DD];
__device__ __align__(16) float g_bcvo[DD];
__device__ __align__(16) __nv_bfloat16 g_q_h[NSD],  g_q_l[NSD];
__device__ __align__(16) __nv_bfloat16 g_k_h[NSD],  g_k_l[NSD];
__device__ __align__(16) __nv_bfloat16 g_vt_h[NSD], g_vt_l[NSD];
__device__ __align__(16) __nv_bfloat16 g_p_h[NSS],  g_p_l[NSS];
__device__ __align__(16) float g_v[NSD];
__device__ __align__(16) float g_P[NSS];

// ---------------------------------------------------------------------------
// bf16x3 HMMA GEMM: C = scale*(A @ B^T) (+ bias)
//   A: hi/lo bf16 [M,K]; B: hi/lo bf16 [N,K]; both K-major.
//   CTA tile 128x128, BK=32, 4-stage cp.async (3 chunks in flight),
//   8 warps (4m x 2n, 32x64 each). 80B smem rows -> conflict-free ldmatrix.
//   (R6/R8 configuration — proven optimum; R7/R10 variants regressed.)
// ---------------------------------------------------------------------------
#define ROWB 80
#define MATB (128 * ROWB)            // 10240 B
#define STAGEB (4 * MATB)            // 40960 B
#define NSTAGE 4
#define GEMM_SMEM (NSTAGE * STAGEB)  // 163840 B

template<bool HAS_BIAS, bool OUT_F32, bool OUT_HL>
__global__ __launch_bounds__(256, 1)
void gemm_bf16x3(const __nv_bfloat16* __restrict__ Ah, const __nv_bfloat16* __restrict__ Al,
                 const __nv_bfloat16* __restrict__ Bh, const __nv_bfloat16* __restrict__ Bl,
                 const float* __restrict__ bias,
                 float* __restrict__ Cf,
                 __nv_bfloat16* __restrict__ Ch, __nv_bfloat16* __restrict__ Cl,
                 int M, int N, int K, float scale,
                 size_t sA, size_t sB, size_t sC)
{
    extern __shared__ char smem[];
    const uint32_t sbase = smem_u32(smem);
    const int tid  = threadIdx.x;
    const int lane = tid & 31;
    const int wid  = tid >> 5;
    const int wm   = wid & 3;
    const int wn   = wid >> 2;
    const size_t z = blockIdx.z;
    Ah += z * sA;  Al += z * sA;
    Bh += z * sB;  Bl += z * sB;
    if (OUT_F32) Cf += z * sC;
    if (OUT_HL)  { Ch += z * sC; Cl += z * sC; }
    const int m0 = blockIdx.y * 128;
    const int n0 = blockIdx.x * 128;
    const int NC = K >> 5;

    auto load_stage = [&](int c, int s) {
        const uint32_t st = sbase + s * STAGEB;
        const int k0 = c * 32;
        #pragma unroll
        for (int i = 0; i < 2; i++) {
            int cid = tid + i * 256;
            int row = cid >> 2, kc = cid & 3;
            uint32_t so = st + row * ROWB + kc * 16;
            size_t ga = (size_t)(m0 + row) * K + k0 + kc * 8;
            size_t gb = (size_t)(n0 + row) * K + k0 + kc * 8;
            CP_ASYNC16(so,            Ah + ga);
            CP_ASYNC16(so + MATB,     Al + ga);
            CP_ASYNC16(so + 2 * MATB, Bh + gb);
            CP_ASYNC16(so + 3 * MATB, Bl + gb);
        }
        CP_COMMIT();
    };

    float acc[2][8][4];
    #pragma unroll
    for (int mi = 0; mi < 2; mi++)
        #pragma unroll
        for (int ni = 0; ni < 8; ni++)
            #pragma unroll
            for (int r = 0; r < 4; r++) acc[mi][ni][r] = 0.f;

    load_stage(0, 0);
    load_stage(1, 1);
    load_stage(2, 2);

    const int a_row = lane & 15;
    const int a_k8  = lane >> 4;
    const int b_row = (lane & 7) + ((lane >> 4) << 3);
    const int b_k8  = (lane >> 3) & 1;

    for (int c = 0; c < NC; c++) {
        if (c + 3 <= NC)      asm volatile("cp.async.wait_group 2;");
        else if (c + 2 == NC) asm volatile("cp.async.wait_group 1;");
        else                  asm volatile("cp.async.wait_group 0;");
        __syncthreads();

        if (c + 3 < NC) load_stage(c + 3, (c + 3) & 3);

        const uint32_t stg = sbase + (c & 3) * STAGEB;
        #pragma unroll
        for (int ks = 0; ks < 2; ks++) {
            uint32_t ah[2][4], al[2][4];
            #pragma unroll
            for (int mi = 0; mi < 2; mi++) {
                uint32_t ra = stg + (wm * 32 + mi * 16 + a_row) * ROWB
                            + (ks * 16 + a_k8 * 8) * 2;
                ldsm4(ah[mi], ra);
                ldsm4(al[mi], ra + MATB);
            }
            #pragma unroll
            for (int ng = 0; ng < 4; ng++) {
                uint32_t rb = stg + 2 * MATB
                            + (wn * 64 + ng * 16 + b_row) * ROWB
                            + (ks * 16 + b_k8 * 8) * 2;
                uint32_t bh4[4], bl4[4];
                ldsm4(bh4, rb);
                ldsm4(bl4, rb + MATB);
                #pragma unroll
                for (int half = 0; half < 2; half++) {
                    const int ni = ng * 2 + half;
                    #pragma unroll
                    for (int mi = 0; mi < 2; mi++) {
                        mma16816(acc[mi][ni], ah[mi], bh4[half * 2], bh4[half * 2 + 1]);
                        mma16816(acc[mi][ni], ah[mi], bl4[half * 2], bl4[half * 2 + 1]);
                        mma16816(acc[mi][ni], al[mi], bh4[half * 2], bh4[half * 2 + 1]);
                    }
                }
            }
        }
    }

    #pragma unroll
    for (int mi = 0; mi < 2; mi++) {
        const int r0 = m0 + wm * 32 + mi * 16 + (lane >> 2);
        #pragma unroll
        for (int ni = 0; ni < 8; ni++) {
            const int col = n0 + wn * 64 + ni * 8 + (lane & 3) * 2;
            float c0 = acc[mi][ni][0] * scale;
            float c1 = acc[mi][ni][1] * scale;
            float c2 = acc[mi][ni][2] * scale;
            float c3 = acc[mi][ni][3] * scale;
            if (HAS_BIAS) {
                float bx = __ldg(bias + col), by = __ldg(bias + col + 1);
                c0 += bx; c1 += by; c2 += bx; c3 += by;
            }
            if (OUT_F32) {
                *(float2*)(Cf + (size_t)r0 * N + col)       = make_float2(c0, c1);
                *(float2*)(Cf + (size_t)(r0 + 8) * N + col) = make_float2(c2, c3);
            }
            if (OUT_HL) {
                __nv_bfloat16 h0 = __float2bfloat16_rn(c0);
                __nv_bfloat16 h1 = __float2bfloat16_rn(c1);
                __nv_bfloat16 h2 = __float2bfloat16_rn(c2);
                __nv_bfloat16 h3 = __float2bfloat16_rn(c3);
                *(__nv_bfloat162*)(Ch + (size_t)r0 * N + col)       = __nv_bfloat162(h0, h1);
                *(__nv_bfloat162*)(Ch + (size_t)(r0 + 8) * N + col) = __nv_bfloat162(h2, h3);
                *(__nv_bfloat162*)(Cl + (size_t)r0 * N + col) = __nv_bfloat162(
                    __float2bfloat16_rn(c0 - __bfloat162float(h0)),
                    __float2bfloat16_rn(c1 - __bfloat162float(h1)));
                *(__nv_bfloat162*)(Cl + (size_t)(r0 + 8) * N + col) = __nv_bfloat162(
                    __float2bfloat16_rn(c2 - __bfloat162float(h2)),
                    __float2bfloat16_rn(c3 - __bfloat162float(h3)));
            }
        }
    }
}

// ---------------------------------------------------------------------------
// fp32 -> bf16 hi/lo elementwise split
// ---------------------------------------------------------------------------
__global__ __launch_bounds__(256)
void split_kernel(const float4* __restrict__ src,
                  __nv_bfloat162* __restrict__ dh, __nv_bfloat162* __restrict__ dl, int n4)
{
    int i = blockIdx.x * blockDim.x + threadIdx.x;
    if (i >= n4) return;
    float4 v = src[i];
    __nv_bfloat16 hx = __float2bfloat16_rn(v.x), hy = __float2bfloat16_rn(v.y);
    __nv_bfloat16 hz = __float2bfloat16_rn(v.z), hw = __float2bfloat16_rn(v.w);
    dh[i * 2 + 0] = __nv_bfloat162(hx, hy);
    dh[i * 2 + 1] = __nv_bfloat162(hz, hw);
    dl[i * 2 + 0] = __nv_bfloat162(__float2bfloat16_rn(v.x - __bfloat162float(hx)),
                                   __float2bfloat16_rn(v.y - __bfloat162float(hy)));
    dl[i * 2 + 1] = __nv_bfloat162(__float2bfloat16_rn(v.z - __bfloat162float(hz)),
                                   __float2bfloat16_rn(v.w - __bfloat162float(hw)));
}

// ---------------------------------------------------------------------------
// fp32 [R,C] -> transposed bf16 hi/lo [C,R]  (batched via z)
// ---------------------------------------------------------------------------
__global__ __launch_bounds__(256)
void transpose_split_kernel(const float* __restrict__ src,
                            __nv_bfloat16* __restrict__ dh, __nv_bfloat16* __restrict__ dl,
                            int R, int C)
{
    __shared__ float tile[32][33];
    size_t z = blockIdx.z;
    size_t nb = (size_t)R * C;
    src += z * nb; dh += z * nb; dl += z * nb;
    int c0 = blockIdx.x * 32, r0 = blockIdx.y * 32;
    int tx = threadIdx.x & 31, ty = threadIdx.x >> 5;
    for (int i = ty; i < 32; i += 8)
        tile[i][tx] = src[(size_t)(r0 + i) * C + c0 + tx];
    __syncthreads();
    for (int i = ty; i < 32; i += 8) {
        float v = tile[tx][i];
        __nv_bfloat16 hi = __float2bfloat16_rn(v);
        size_t off = (size_t)(c0 + i) * R + r0 + tx;
        dh[off] = hi;
        dl[off] = __float2bfloat16_rn(v - __bfloat162float(hi));
    }
}

// ---------------------------------------------------------------------------
// Combined bias: bc[i] = (b2 ? b2[i] : 0) + sum_l bsrc[l] * W[l*DD + i]
// ---------------------------------------------------------------------------
__global__ __launch_bounds__(256)
void bias_combine_kernel(const float* __restrict__ bsrc, const float* __restrict__ W,
                         const float* __restrict__ b2, float* __restrict__ bc)
{
    int i = blockIdx.x * 256 + threadIdx.x;
    float s = b2 ? b2[i] : 0.0f;
    for (int l = 0; l < DD; l++) s += bsrc[l] * W[(size_t)l * DD + i];
    bc[i] = s;
}

// ---------------------------------------------------------------------------
// Row softmax: fp32 scores -> bf16 hi/lo attention weights (FMA-pipe exp)
// ---------------------------------------------------------------------------
__global__ __launch_bounds__(256)
void softmax_kernel(const float* __restrict__ P,
                    __nv_bfloat16* __restrict__ Ph, __nv_bfloat16* __restrict__ Pl)
{
    const size_t roff = (size_t)blockIdx.x * SS;
    const float* row = P + roff;
    const int tid = threadIdx.x;

    float4 v[4];
    #pragma unroll
    for (int i = 0; i < 4; i++)
        v[i] = *(const float4*)(row + (size_t)(tid + i * 256) * 4);

    float m = -INFINITY;
    #pragma unroll
    for (int i = 0; i < 4; i++)
        m = fmaxf(m, fmaxf(fmaxf(v[i].x, v[i].y), fmaxf(v[i].z, v[i].w)));
    #pragma unroll
    for (int off = 16; off > 0; off >>= 1)
        m = fmaxf(m, __shfl_xor_sync(0xFFFFFFFFu, m, off));

    __shared__ float smax[8], ssum[8];
    const int warp = tid >> 5, lane = tid & 31;
    if (lane == 0) smax[warp] = m;
    __syncthreads();
    if (warp == 0) {
        float t = (lane < 8) ? smax[lane] : -INFINITY;
        #pragma unroll
        for (int off = 4; off > 0; off >>= 1)
            t = fmaxf(t, __shfl_xor_sync(0xFFFFFFFFu, t, off));
        if (lane == 0) smax[0] = t;
    }
    __syncthreads();
    m = smax[0];

    float s = 0.f;
    #pragma unroll
    for (int i = 0; i < 4; i++) {
        v[i].x = fast_exp(v[i].x - m); v[i].y = fast_exp(v[i].y - m);
        v[i].z = fast_exp(v[i].z - m); v[i].w = fast_exp(v[i].w - m);
        s += v[i].x + v[i].y + v[i].z + v[i].w;
    }
    #pragma unroll
    for (int off = 16; off > 0; off >>= 1)
        s += __shfl_xor_sync(0xFFFFFFFFu, s, off);
    if (lane == 0) ssum[warp] = s;
    __syncthreads();
    if (warp == 0) {
        float t = (lane < 8) ? ssum[lane] : 0.f;
        #pragma unroll
        for (int off = 4; off > 0; off >>= 1)
            t += __shfl_xor_sync(0xFFFFFFFFu, t, off);
        if (lane == 0) ssum[0] = t;
    }
    __syncthreads();
    const float inv = 1.0f / ssum[0];

    #pragma unroll
    for (int i = 0; i < 4; i++) {
        size_t base = roff + (size_t)(tid + i * 256) * 4;
        float a = v[i].x * inv, b = v[i].y * inv, c = v[i].z * inv, d = v[i].w * inv;
        __nv_bfloat16 ha = __float2bfloat16_rn(a), hb = __float2bfloat16_rn(b);
        __nv_bfloat16 hc = __float2bfloat16_rn(c), hd = __float2bfloat16_rn(d);
        *(__nv_bfloat162*)(Ph + base)     = __nv_bfloat162(ha, hb);
        *(__nv_bfloat162*)(Ph + base + 2) = __nv_bfloat162(hc, hd);
        *(__nv_bfloat162*)(Pl + base) = __nv_bfloat162(
            __float2bfloat16_rn(a - __bfloat162float(ha)),
            __float2bfloat16_rn(b - __bfloat162float(hb)));
        *(__nv_bfloat162*)(Pl + base + 2) = __nv_bfloat162(
            __float2bfloat16_rn(c - __bfloat162float(hc)),
            __float2bfloat16_rn(d - __bfloat162float(hd)));
    }
}

// ---------------------------------------------------------------------------
// Launch
// ---------------------------------------------------------------------------
extern "C" void kernel_launch(void* const* d_in, const int* in_sizes, int n_in,
                              void* d_out, int out_size)
{
    const float* query = (const float*)d_in[0];
    const float* key_  = (const float*)d_in[1];
    const float* value = (const float*)d_in[2];
    const float* Wh    = (const float*)d_in[3];
    const float* bh    = (const float*)d_in[4];
    const float* Wk    = (const float*)d_in[5];
    const float* bk    = (const float*)d_in[6];
    const float* Wv    = (const float*)d_in[7];
    const float* bv    = (const float*)d_in[8];
    const float* Wo    = (const float*)d_in[9];
    const float* bo    = (const float*)d_in[10];
    float* out = (float*)d_out;

    struct Ptrs {
        __nv_bfloat16 *iq_h, *iq_l, *ik_h, *ik_l, *iv_h, *iv_l;
        __nv_bfloat16 *w1_h, *w1_l, *w2_h, *w2_l, *w3_h, *w3_l, *w4_h, *w4_l;
        __nv_bfloat16 *whp_h, *whp_l, *wck_h, *wck_l, *whwv_h, *whwv_l, *wcvo_h, *wcvo_l;
        __nv_bfloat16 *q_h, *q_l, *k_h, *k_l, *vt_h, *vt_l;
        __nv_bfloat16 *p_h, *p_l;
        float *bck, *bcv, *bcvo, *v, *P;
    };
    static Ptrs p = {};
    static bool inited = false;
    if (!inited) {
        inited = true;
        cudaGetSymbolAddress((void**)&p.iq_h, g_iq_h); cudaGetSymbolAddress((void**)&p.iq_l, g_iq_l);
        cudaGetSymbolAddress((void**)&p.ik_h, g_ik_h); cudaGetSymbolAddress((void**)&p.ik_l, g_ik_l);
        cudaGetSymbolAddress((void**)&p.iv_h, g_iv_h); cudaGetSymbolAddress((void**)&p.iv_l, g_iv_l);
        cudaGetSymbolAddress((void**)&p.w1_h, g_w1_h); cudaGetSymbolAddress((void**)&p.w1_l, g_w1_l);
        cudaGetSymbolAddress((void**)&p.w2_h, g_w2_h); cudaGetSymbolAddress((void**)&p.w2_l, g_w2_l);
        cudaGetSymbolAddress((void**)&p.w3_h, g_w3_h); cudaGetSymbolAddress((void**)&p.w3_l, g_w3_l);
        cudaGetSymbolAddress((void**)&p.w4_h, g_w4_h); cudaGetSymbolAddress((void**)&p.w4_l, g_w4_l);
        cudaGetSymbolAddress((void**)&p.whp_h, g_whp_h); cudaGetSymbolAddress((void**)&p.whp_l, g_whp_l);
        cudaGetSymbolAddress((void**)&p.wck_h, g_wck_h); cudaGetSymbolAddress((void**)&p.wck_l, g_wck_l);
        cudaGetSymbolAddress((void**)&p.whwv_h, g_whwv_h); cudaGetSymbolAddress((void**)&p.whwv_l, g_whwv_l);
        cudaGetSymbolAddress((void**)&p.wcvo_h, g_wcvo_h); cudaGetSymbolAddress((void**)&p.wcvo_l, g_wcvo_l);
        cudaGetSymbolAddress((void**)&p.q_h,  g_q_h);  cudaGetSymbolAddress((void**)&p.q_l,  g_q_l);
        cudaGetSymbolAddress((void**)&p.k_h,  g_k_h);  cudaGetSymbolAddress((void**)&p.k_l,  g_k_l);
        cudaGetSymbolAddress((void**)&p.vt_h, g_vt_h); cudaGetSymbolAddress((void**)&p.vt_l, g_vt_l);
        cudaGetSymbolAddress((void**)&p.p_h,  g_p_h);  cudaGetSymbolAddress((void**)&p.p_l,  g_p_l);
        cudaGetSymbolAddress((void**)&p.bck,  g_bck);  cudaGetSymbolAddress((void**)&p.bcv,  g_bcv);
        cudaGetSymbolAddress((void**)&p.bcvo, g_bcvo);
        cudaGetSymbolAddress((void**)&p.v,    g_v);    cudaGetSymbolAddress((void**)&p.P,    g_P);
        cudaFuncSetAttribute(gemm_bf16x3<true,  false, true >, cudaFuncAttributeMaxDynamicSharedMemorySize, GEMM_SMEM);
        cudaFuncSetAttribute(gemm_bf16x3<true,  true,  false>, cudaFuncAttributeMaxDynamicSharedMemorySize, GEMM_SMEM);
        cudaFuncSetAttribute(gemm_bf16x3<false, true,  false>, cudaFuncAttributeMaxDynamicSharedMemorySize, GEMM_SMEM);
        cudaFuncSetAttribute(gemm_bf16x3<false, false, true >, cudaFuncAttributeMaxDynamicSharedMemorySize, GEMM_SMEM);
    }

    const int M = BB * SS;                  // 16384
    const size_t sd = (size_t)SS * DD;
    const size_t ss = (size_t)SS * SS;
    dim3 blk(256);

    // --- prep: split inputs / weights, fold chained projections ---
    {
        int n4 = (int)(NSD / 4);
        int grid = (n4 + 255) / 256;
        split_kernel<<<grid, 256>>>((const float4*)query, (__nv_bfloat162*)p.iq_h, (__nv_bfloat162*)p.iq_l, n4);
        split_kernel<<<grid, 256>>>((const float4*)key_,  (__nv_bfloat162*)p.ik_h, (__nv_bfloat162*)p.ik_l, n4);
        split_kernel<<<grid, 256>>>((const float4*)value, (__nv_bfloat162*)p.iv_h, (__nv_bfloat162*)p.iv_l, n4);
        int w4 = (int)(NW / 4);
        split_kernel<<<(w4 + 255) / 256, 256>>>((const float4*)Wh, (__nv_bfloat162*)p.whp_h, (__nv_bfloat162*)p.whp_l, w4);
        dim3 gw(DD / 32, DD / 32, 1);
        transpose_split_kernel<<<gw, 256>>>(Wh, p.w1_h, p.w1_l, DD, DD);
        transpose_split_kernel<<<gw, 256>>>(Wk, p.w2_h, p.w2_l, DD, DD);
        transpose_split_kernel<<<gw, 256>>>(Wv, p.w3_h, p.w3_l, DD, DD);
        transpose_split_kernel<<<gw, 256>>>(Wo, p.w4_h, p.w4_l, DD, DD);

        dim3 gc(DD / 128, DD / 128, 1);
        // (Wh·Wk)^T = gemm(WkT, Wh-plain):  wck[m,n] = sum_k Wk[k,m] Wh[n,k]
        gemm_bf16x3<false, false, true><<<gc, blk, GEMM_SMEM>>>(
            p.w2_h, p.w2_l, p.whp_h, p.whp_l, nullptr, nullptr, p.wck_h, p.wck_l,
            DD, DD, DD, 1.f, 0, 0, 0);
        // (Wh·Wv) plain = gemm(Wh-plain, WvT):  whwv[m,n] = sum_k Wh[m,k] Wv[k,n]
        gemm_bf16x3<false, false, true><<<gc, blk, GEMM_SMEM>>>(
            p.whp_h, p.whp_l, p.w3_h, p.w3_l, nullptr, nullptr, p.whwv_h, p.whwv_l,
            DD, DD, DD, 1.f, 0, 0, 0);
        // (Wh·Wv·Wo)^T = gemm(WoT, WhWv-plain): wcvo[m,n] = sum_k Wo[k,m] (WhWv)[n,k]
        gemm_bf16x3<false, false, true><<<gc, blk, GEMM_SMEM>>>(
            p.w4_h, p.w4_l, p.whwv_h, p.whwv_l, nullptr, nullptr, p.wcvo_h, p.wcvo_l,
            DD, DD, DD, 1.f, 0, 0, 0);

        // biases: bck = bh·Wk + bk ; bcv = bh·Wv + bv ; bcvo = bcv·Wo
        bias_combine_kernel<<<DD / 256, 256>>>(bh, Wk, bk, p.bck);
        bias_combine_kernel<<<DD / 256, 256>>>(bh, Wv, bv, p.bcv);
        bias_combine_kernel<<<DD / 256, 256>>>(p.bcv, Wo, nullptr, p.bcvo);
    }

    dim3 gproj(DD / 128, M / 128, 1);       // (8, 128)

    // 1) q = query @ Wh + bh
    gemm_bf16x3<true, false, true><<<gproj, blk, GEMM_SMEM>>>(
        p.iq_h, p.iq_l, p.w1_h, p.w1_l, bh, nullptr, p.q_h, p.q_l,
        M, DD, DD, 1.f, 0, 0, 0);
    // 2) k = key @ (Wh Wk) + (bh Wk + bk)
    gemm_bf16x3<true, false, true><<<gproj, blk, GEMM_SMEM>>>(
        p.ik_h, p.ik_l, p.wck_h, p.wck_l, p.bck, nullptr, p.k_h, p.k_l,
        M, DD, DD, 1.f, 0, 0, 0);
    // 3) v' = value @ (Wh Wv Wo) + ((bh Wv + bv) Wo)  -> fp32, then transpose+split
    gemm_bf16x3<true, true, false><<<gproj, blk, GEMM_SMEM>>>(
        p.iv_h, p.iv_l, p.wcvo_h, p.wcvo_l, p.bcvo, p.v, nullptr, nullptr,
        M, DD, DD, 1.f, 0, 0, 0);
    {
        dim3 gv(DD / 32, SS / 32, BB);
        transpose_split_kernel<<<gv, 256>>>(p.v, p.vt_h, p.vt_l, SS, DD);
    }

    // 4) P = (q @ k^T) / 1024   (batched)
    dim3 gqk(SS / 128, SS / 128, BB);       // (32, 32, 4)
    gemm_bf16x3<false, true, false><<<gqk, blk, GEMM_SMEM>>>(
        p.q_h, p.q_l, p.k_h, p.k_l, nullptr, p.P, nullptr, nullptr,
        SS, SS, DD, 1.0f / (float)DD, sd, sd, ss);

    // 5) softmax -> bf16 hi/lo attn (FMA-pipe exp)
    softmax_kernel<<<BB * SS, 256>>>(p.P, p.p_h, p.p_l);

    // 6) out = attn @ v' + bo   (batched; final output — out-projection folded away)
    dim3 gpv(DD / 128, SS / 128, BB);       // (8, 32, 4)
    gemm_bf16x3<true, true, false><<<gpv, blk, GEMM_SMEM>>>(
        p.p_h, p.p_l, p.vt_h, p.vt_l, bo, out, nullptr, nullptr,
        SS, DD, SS, 1.f, ss, sd, sd);
}